// round 13
// baseline (speedup 1.0000x reference)
#include <cuda_runtime.h>
#include <cstdint>

// x: (B=64, NU=32, IC=256, UNIT=128) fp32, contiguous.
// Reference reinterprets flat buffer as (B, IC, NU, UNIT):
//   u_hat[b,i,j,u] = x_flat[b*1048576 + i*4096 + j*128 + u]
// s[b,j,u] = (1/256) * sum_i u_hat[b,i,j,u]; then squash over u (128 elems).
// Output: (B, NU, UNIT) = 262144 fp32.
//
// R13: Blackwell 256-bit loads (ld.global.cs.v8.b32 -> LDG.256). One block
// per (b, j-pair): 1024 blocks x 256 threads (8 warps), warps i-interleaved
// (i = warp + 8k; the proven 8-consecutive-row window from R10, 43.1us).
// Each lane loads 32 CONTIGUOUS bytes; a warp's single load = 1KB dense
// request covering columns {j0, j1} of one row. Halves LDG count and
// L1tex wavefront-queue entries per byte vs the LDG.128 champion.
// Lane f-mapping: float4 slot f = lane*2+{0,1}; f<32 -> j0 u4=f,
// f>=32 -> j1 u4=f-32. Epilogue: warp 0 squashes j0, warp 1 squashes j1.

static constexpr int IC       = 256;
static constexpr int BLOCKS   = 64 * 16;        // (b, j-pair) = 1024
static constexpr int STRIDE4  = 4096 / 4;       // i-stride in float4 units
static constexpr int THREADS  = 256;            // 8 warps
static constexpr int IC_PER_W = IC / 8;         // 32 rows per warp

__device__ __forceinline__ void ldg256_cs(const float4* p, float4& lo, float4& hi) {
    uint32_t r0, r1, r2, r3, r4, r5, r6, r7;
    asm volatile("ld.global.cs.v8.b32 {%0,%1,%2,%3,%4,%5,%6,%7}, [%8];"
                 : "=r"(r0), "=r"(r1), "=r"(r2), "=r"(r3),
                   "=r"(r4), "=r"(r5), "=r"(r6), "=r"(r7)
                 : "l"(p));
    lo.x = __uint_as_float(r0); lo.y = __uint_as_float(r1);
    lo.z = __uint_as_float(r2); lo.w = __uint_as_float(r3);
    hi.x = __uint_as_float(r4); hi.y = __uint_as_float(r5);
    hi.z = __uint_as_float(r6); hi.w = __uint_as_float(r7);
}

__global__ __launch_bounds__(THREADS, 4)
void capsule_squash_kernel(const float4* __restrict__ x4,
                           float4* __restrict__ out4) {
    const int warp = threadIdx.x >> 5;
    const int lane = threadIdx.x & 31;

    const int b  = blockIdx.x >> 4;             // 64 b values
    const int jp = blockIdx.x & 15;             // j-pair: j0=2jp, j1=2jp+1
    // float4 base: b*262144 + jp*64 (1KB window) + row(warp)*1024 + lane*2
    const int base4 = b * (1048576 / 4) + jp * (256 / 4)
                    + warp * STRIDE4 + lane * 2;

    float4 a0 = make_float4(0.f, 0.f, 0.f, 0.f);   // k even, lo
    float4 a1 = make_float4(0.f, 0.f, 0.f, 0.f);   // k even, hi
    float4 b0 = make_float4(0.f, 0.f, 0.f, 0.f);   // k odd,  lo
    float4 b1 = make_float4(0.f, 0.f, 0.f, 0.f);   // k odd,  hi

#pragma unroll 8
    for (int k = 0; k < IC_PER_W; k += 2) {
        float4 lA, hA, lB, hB;
        ldg256_cs(&x4[base4 + (k    ) * (8 * STRIDE4)], lA, hA);
        ldg256_cs(&x4[base4 + (k + 1) * (8 * STRIDE4)], lB, hB);
        a0.x += lA.x; a0.y += lA.y; a0.z += lA.z; a0.w += lA.w;
        a1.x += hA.x; a1.y += hA.y; a1.z += hA.z; a1.w += hA.w;
        b0.x += lB.x; b0.y += lB.y; b0.z += lB.z; b0.w += lB.w;
        b1.x += hB.x; b1.y += hB.y; b1.z += hB.z; b1.w += hB.w;
    }
    float4 s0 = make_float4(a0.x + b0.x, a0.y + b0.y, a0.z + b0.z, a0.w + b0.w);
    float4 s1 = make_float4(a1.x + b1.x, a1.y + b1.y, a1.z + b1.z, a1.w + b1.w);

    // part[w][f]: f = lane*2 + {0,1} in [0,64); f<32 -> j0 slot f, else j1 slot f-32
    __shared__ float4 part[8][64];
    part[warp][lane * 2    ] = s0;
    part[warp][lane * 2 + 1] = s1;
    __syncthreads();

    if (warp < 2) {                              // warp 0 -> j0, warp 1 -> j1
        const int f = warp * 32 + lane;
        float4 t = part[0][f];
#pragma unroll
        for (int w = 1; w < 8; w++) {
            float4 p = part[w][f];
            t.x += p.x; t.y += p.y; t.z += p.z; t.w += p.w;
        }
        const float c = 1.0f / 256.0f;
        t.x *= c; t.y *= c; t.z *= c; t.w *= c;

        // mag_sq over the 128-element unit dim (warp-wide)
        float sq = t.x * t.x + t.y * t.y + t.z * t.z + t.w * t.w;
#pragma unroll
        for (int off = 16; off > 0; off >>= 1)
            sq += __shfl_xor_sync(0xffffffffu, sq, off);

        const float mag   = sqrtf(sq);
        const float scale = sq / (1.0f + sq) / (mag + 1e-5f);

        const int g = (blockIdx.x << 1) + warp;  // group = b*32 + j
        out4[g * 32 + lane] = make_float4(t.x * scale, t.y * scale,
                                          t.z * scale, t.w * scale);
    }
}

extern "C" void kernel_launch(void* const* d_in, const int* in_sizes, int n_in,
                              void* d_out, int out_size) {
    const float4* x4 = (const float4*)d_in[0];
    float4* out4 = (float4*)d_out;
    capsule_squash_kernel<<<BLOCKS, THREADS>>>(x4, out4);
}

// round 14
// speedup vs baseline: 1.0163x; 1.0163x over previous
#include <cuda_runtime.h>

// x: (B=64, NU=32, IC=256, UNIT=128) fp32, contiguous.
// Reference reinterprets flat buffer as (B, IC, NU, UNIT):
//   u_hat[b,i,j,u] = x_flat[b*1048576 + i*4096 + j*128 + u]
// s[b,j,u] = (1/256) * sum_i u_hat[b,i,j,u]; then squash over u (128 elems).
// Output: (B, NU, UNIT) = 262144 fp32.
//
// FINAL (= R10 champion). 256-thread blocks (8 warps), one block per (b,j)
// group (2048 blocks). Warps i-INTERLEAVED (i = warp + 8k): block live
// window = 8 CONSECUTIVE 16KB rows x 512B — measured optimum (4-row
// slower, 16-row equal). Dual independent accumulators +
// __launch_bounds__(256,4) (64-reg budget) for front-batched LDG.128;
// __ldcs read-once streaming. Epilogue: smem combine + warp-0 squash.
//
// Session evidence (13 rounds): concurrency, wave shape, persistence,
// request width (512B/1KB), sequential-vs-strided streams, reg/MLP budget,
// accumulator tree depth, row-window size, and LDG.256 all measured; every
// structure converges at 6.35-6.51 TB/s (~81% of 8TB/s spec) — the
// platform's practical fp32-stream ceiling at NAT clocks (sequential
// stream R7 hit the same number, so it is path-, not pattern-, limited).
// Best bench: 43.10us (reproduced 43.49us); ncu kernel dur 42.2us vs the
// 41.3us bandwidth floor at the observed ceiling.

static constexpr int IC       = 256;
static constexpr int GROUPS   = 64 * 32;        // 2048 blocks
static constexpr int STRIDE4  = 4096 / 4;       // i-stride in float4 units
static constexpr int THREADS  = 256;            // 8 warps/block
static constexpr int IC_PER_W = IC / 8;         // 32 rows per warp

__global__ __launch_bounds__(THREADS, 4)
void capsule_squash_kernel(const float4* __restrict__ x4,
                           float4* __restrict__ out4) {
    const int g    = blockIdx.x;                // group = b*32 + j
    const int warp = threadIdx.x >> 5;
    const int lane = threadIdx.x & 31;

    const int b = g >> 5;
    const int j = g & 31;
    // warp w reads rows i = w, w+8, w+16, ... (interleaved across 8 warps)
    const int base4 = b * (1048576 / 4) + j * (128 / 4) + lane
                    + warp * STRIDE4;

    float4 sA = make_float4(0.f, 0.f, 0.f, 0.f);
    float4 sB = make_float4(0.f, 0.f, 0.f, 0.f);

#pragma unroll 8
    for (int k = 0; k < IC_PER_W; k += 2) {
        float4 vA = __ldcs(&x4[base4 + (k    ) * (8 * STRIDE4)]);
        float4 vB = __ldcs(&x4[base4 + (k + 1) * (8 * STRIDE4)]);
        sA.x += vA.x; sA.y += vA.y; sA.z += vA.z; sA.w += vA.w;
        sB.x += vB.x; sB.y += vB.y; sB.z += vB.z; sB.w += vB.w;
    }
    float4 s = make_float4(sA.x + sB.x, sA.y + sB.y,
                           sA.z + sB.z, sA.w + sB.w);

    __shared__ float4 part[8][32];
    part[warp][lane] = s;
    __syncthreads();

    if (warp == 0) {
        float4 t = part[0][lane];
#pragma unroll
        for (int w = 1; w < 8; w++) {
            float4 p = part[w][lane];
            t.x += p.x; t.y += p.y; t.z += p.z; t.w += p.w;
        }
        const float c = 1.0f / 256.0f;
        t.x *= c; t.y *= c; t.z *= c; t.w *= c;

        // mag_sq over the 128-element unit dim (warp-wide)
        float sq = t.x * t.x + t.y * t.y + t.z * t.z + t.w * t.w;
#pragma unroll
        for (int off = 16; off > 0; off >>= 1)
            sq += __shfl_xor_sync(0xffffffffu, sq, off);

        const float mag   = sqrtf(sq);
        const float scale = sq / (1.0f + sq) / (mag + 1e-5f);

        out4[g * 32 + lane] = make_float4(t.x * scale, t.y * scale,
                                          t.z * scale, t.w * scale);
    }
}

extern "C" void kernel_launch(void* const* d_in, const int* in_sizes, int n_in,
                              void* d_out, int out_size) {
    const float4* x4 = (const float4*)d_in[0];
    float4* out4 = (float4*)d_out;
    capsule_squash_kernel<<<GROUPS, THREADS>>>(x4, out4);
}

// round 15
// speedup vs baseline: 1.0171x; 1.0007x over previous
#include <cuda_runtime.h>

// x: (B=64, NU=32, IC=256, UNIT=128) fp32, contiguous.
// Reference reinterprets flat buffer as (B, IC, NU, UNIT):
//   u_hat[b,i,j,u] = x_flat[b*1048576 + i*4096 + j*128 + u]
// s[b,j,u] = (1/256) * sum_i u_hat[b,i,j,u]; then squash over u (128 elems).
// Output: (B, NU, UNIT) = 262144 fp32.
//
// FINAL (R10 champion + full unroll). 256-thread blocks (8 warps), one
// block per (b,j) group (2048 blocks). Warps i-INTERLEAVED (i = warp + 8k):
// block live window = 8 CONSECUTIVE 16KB rows x 512B (measured optimum;
// 4-row slower, 16-row equal). Dual independent accumulators,
// __launch_bounds__(256,4) (64-reg budget), __ldcs read-once streaming.
// This round: fully unroll the 16-iteration k-loop (was unroll 8) so the
// whole 32-load stream is schedulable with no mid-loop branch.
//
// Champion reproduction: 43.10 / 43.49 / 43.07 us across three runs;
// ncu 41.6us vs 41.0us bandwidth floor at the observed 6541 GB/s ceiling
// (~98.5% of the platform's demonstrated fp32-stream limit; 13 structural
// variants all converge at 6.35-6.54 TB/s, incl. a perfectly sequential
// stream — the ceiling is path-level, not pattern-level).

static constexpr int IC       = 256;
static constexpr int GROUPS   = 64 * 32;        // 2048 blocks
static constexpr int STRIDE4  = 4096 / 4;       // i-stride in float4 units
static constexpr int THREADS  = 256;            // 8 warps/block
static constexpr int IC_PER_W = IC / 8;         // 32 rows per warp

__global__ __launch_bounds__(THREADS, 4)
void capsule_squash_kernel(const float4* __restrict__ x4,
                           float4* __restrict__ out4) {
    const int g    = blockIdx.x;                // group = b*32 + j
    const int warp = threadIdx.x >> 5;
    const int lane = threadIdx.x & 31;

    const int b = g >> 5;
    const int j = g & 31;
    // warp w reads rows i = w, w+8, w+16, ... (interleaved across 8 warps)
    const int base4 = b * (1048576 / 4) + j * (128 / 4) + lane
                    + warp * STRIDE4;

    float4 sA = make_float4(0.f, 0.f, 0.f, 0.f);
    float4 sB = make_float4(0.f, 0.f, 0.f, 0.f);

#pragma unroll
    for (int k = 0; k < IC_PER_W; k += 2) {
        float4 vA = __ldcs(&x4[base4 + (k    ) * (8 * STRIDE4)]);
        float4 vB = __ldcs(&x4[base4 + (k + 1) * (8 * STRIDE4)]);
        sA.x += vA.x; sA.y += vA.y; sA.z += vA.z; sA.w += vA.w;
        sB.x += vB.x; sB.y += vB.y; sB.z += vB.z; sB.w += vB.w;
    }
    float4 s = make_float4(sA.x + sB.x, sA.y + sB.y,
                           sA.z + sB.z, sA.w + sB.w);

    __shared__ float4 part[8][32];
    part[warp][lane] = s;
    __syncthreads();

    if (warp == 0) {
        float4 t = part[0][lane];
#pragma unroll
        for (int w = 1; w < 8; w++) {
            float4 p = part[w][lane];
            t.x += p.x; t.y += p.y; t.z += p.z; t.w += p.w;
        }
        const float c = 1.0f / 256.0f;
        t.x *= c; t.y *= c; t.z *= c; t.w *= c;

        // mag_sq over the 128-element unit dim (warp-wide)
        float sq = t.x * t.x + t.y * t.y + t.z * t.z + t.w * t.w;
#pragma unroll
        for (int off = 16; off > 0; off >>= 1)
            sq += __shfl_xor_sync(0xffffffffu, sq, off);

        const float mag   = sqrtf(sq);
        const float scale = sq / (1.0f + sq) / (mag + 1e-5f);

        out4[g * 32 + lane] = make_float4(t.x * scale, t.y * scale,
                                          t.z * scale, t.w * scale);
    }
}

extern "C" void kernel_launch(void* const* d_in, const int* in_sizes, int n_in,
                              void* d_out, int out_size) {
    const float4* x4 = (const float4*)d_in[0];
    float4* out4 = (float4*)d_out;
    capsule_squash_kernel<<<GROUPS, THREADS>>>(x4, out4);
}